// round 6
// baseline (speedup 1.0000x reference)
#include <cuda_runtime.h>
#include <math.h>
#include <stdint.h>

// ---------------- problem constants ----------------
constexpr int Bc   = 2;
constexpr int Sc   = 2048;
constexpr int Hc   = 2048;
constexpr int Tc   = Bc * Sc;      // 4096 tokens
constexpr int Ec   = 8;
constexpr int IM   = 1408;
constexpr int ISH  = 5632;
constexpr int NQc  = 16;
constexpr int NKVc = 2;
constexpr int DHc  = 128;
constexpr float EPSc = 1e-5f;

// rounded+transposed weight scratch offsets (all stored [n][k])
constexpr size_t OFF_WQ  = 0;
constexpr size_t OFF_WK  = OFF_WQ  + (size_t)2048 * 2048;
constexpr size_t OFF_WV  = OFF_WK  + (size_t)2048 * 256;
constexpr size_t OFF_WO  = OFF_WV  + (size_t)2048 * 256;
constexpr size_t OFF_WG  = OFF_WO  + (size_t)2048 * 2048;
constexpr size_t OFF_WU  = OFF_WG  + (size_t)Ec * 2048 * IM;
constexpr size_t OFF_WD  = OFF_WU  + (size_t)Ec * 2048 * IM;
constexpr size_t OFF_SWG = OFF_WD  + (size_t)Ec * IM * 2048;
constexpr size_t OFF_SWU = OFF_SWG + (size_t)2048 * ISH;
constexpr size_t OFF_SWD = OFF_SWU + (size_t)2048 * ISH;
constexpr size_t WR_TOT  = OFF_SWD + (size_t)ISH * 2048;

// ---------------- scratch (device globals; no allocations allowed) ----------------
__device__ float g_wr [WR_TOT];                      // tf32-rounded, transposed weights
__device__ float g_h  [(size_t)Tc * Hc];
__device__ float g_q  [(size_t)Tc * NQc * DHc];
__device__ float g_k  [(size_t)Tc * NKVc * DHc];
__device__ float g_v  [(size_t)Tc * NKVc * DHc];
__device__ float g_vT [(size_t)Bc * NKVc * DHc * Sc]; // V transposed per (b,kv): [bk][d][s]
__device__ float g_sc [(size_t)Bc * NQc * Sc * Sc];  // scores -> probs in place
__device__ float g_ao [(size_t)Tc * Hc];
__device__ float g_x  [(size_t)Tc * Hc];
__device__ float g_t2 [(size_t)Tc * Hc];             // exact (router/sgate)
__device__ float g_t2r[(size_t)Tc * Hc];             // tf32-rounded (GEMM A)
__device__ float g_dw [Tc * Ec];
__device__ int   g_cnt[Ec];
__device__ int   g_list[Ec * Tc];
__device__ float g_mg [(size_t)Ec * Tc * IM];
__device__ float g_mu [(size_t)Ec * Tc * IM];
__device__ float g_moe[(size_t)Tc * Hc];
__device__ float g_sgv[(size_t)Tc * ISH];
__device__ float g_suv[(size_t)Tc * ISH];
__device__ float g_sh [(size_t)Tc * Hc];
__device__ float g_sgate[Tc];

__device__ __forceinline__ float tf32r(float x) {
    uint32_t u;
    asm("cvt.rna.tf32.f32 %0, %1;" : "=r"(u) : "f"(x));
    return __uint_as_float(u);
}

// ---------------- rounded transpose: dst[n*K + k] = tf32r(src[k*N + n]) ----------------
__global__ void round_tr_kernel(const float* __restrict__ src, size_t off, int K, int N) {
    __shared__ float t[32][33];
    const int z = blockIdx.z;
    src += (size_t)z * K * N;
    float* dst = g_wr + off + (size_t)z * K * N;
    const int nb = blockIdx.x * 32, kb = blockIdx.y * 32;
    const int tx = threadIdx.x, ty = threadIdx.y;   // 32 x 8
#pragma unroll
    for (int i = 0; i < 32; i += 8)
        t[ty + i][tx] = src[(size_t)(kb + ty + i) * N + nb + tx];
    __syncthreads();
#pragma unroll
    for (int i = 0; i < 32; i += 8)
        dst[(size_t)(nb + ty + i) * K + kb + tx] = tf32r(t[tx][ty + i]);
}

// ---------------- small kernels ----------------
__global__ void clear_cnt_kernel() {
    if (threadIdx.x < Ec) g_cnt[threadIdx.x] = 0;
}
__global__ void clear_moe_kernel() {
    g_moe[(size_t)blockIdx.x * 256 + threadIdx.x] = 0.f;
}

template<int PHASE>
__global__ void rmsnorm_kernel(const float* __restrict__ xin,
                               const float* __restrict__ scale) {
    __shared__ float red[256];
    const int row = blockIdx.x;
    const float* x = (PHASE == 0) ? (xin + (size_t)row * Hc) : (g_x + (size_t)row * Hc);
    float s = 0.f;
    for (int i = threadIdx.x; i < Hc; i += 256) { float v = x[i]; s += v * v; }
    red[threadIdx.x] = s; __syncthreads();
    for (int o = 128; o > 0; o >>= 1) {
        if (threadIdx.x < o) red[threadIdx.x] += red[threadIdx.x + o];
        __syncthreads();
    }
    const float inv = rsqrtf(red[0] / (float)Hc + EPSc);
    for (int i = threadIdx.x; i < Hc; i += 256) {
        const float v = x[i] * inv * scale[i];
        if (PHASE == 0) {
            g_h[(size_t)row * Hc + i] = tf32r(v);
        } else {
            g_t2 [(size_t)row * Hc + i] = v;
            g_t2r[(size_t)row * Hc + i] = tf32r(v);
        }
    }
}

__global__ void rope_kernel() {
    const int tok  = blockIdx.x;
    const int head = blockIdx.y;
    const int j    = threadIdx.x;         // 0..63
    const int s    = tok & (Sc - 1);
    const float inv = powf(10000.f, -(float)(2 * j) / 128.f);
    const float ang = (float)s * inv;
    float si, c;
    sincosf(ang, &si, &c);
    float* p = (head < NQc) ? (g_q + (size_t)tok * (NQc * DHc) + head * DHc)
                            : (g_k + (size_t)tok * (NKVc * DHc) + (head - NQc) * DHc);
    const float x1 = p[j], x2 = p[j + 64];
    p[j]      = tf32r(x1 * c - x2 * si);
    p[j + 64] = tf32r(x2 * c + x1 * si);
}

// vT[bk][d][s] = v[b*S+s][kv*128+d]
__global__ void vT_kernel() {
    const int i  = blockIdx.x * 256 + threadIdx.x;
    const int s  = i & (Sc - 1);
    const int d  = (i >> 11) & 127;
    const int bk = i >> 18;
    g_vT[i] = g_v[((size_t)((bk >> 1) * Sc + s)) * (NKVc * DHc) + (bk & 1) * DHc + d];
}

__global__ void softmax_kernel() {
    __shared__ float red[256];
    const size_t rid = blockIdx.x;
    const int r   = (int)(rid & (Sc - 1));
    float* sc = g_sc + rid * Sc;
    const int lim = r + 1;
    const int tid = threadIdx.x;
    float m = -1e30f;
    for (int c = tid; c < lim; c += 256) m = fmaxf(m, sc[c]);
    red[tid] = m; __syncthreads();
    for (int o = 128; o > 0; o >>= 1) {
        if (tid < o) red[tid] = fmaxf(red[tid], red[tid + o]);
        __syncthreads();
    }
    m = red[0]; __syncthreads();
    float s = 0.f;
    for (int c = tid; c < lim; c += 256) s += expf(sc[c] - m);
    red[tid] = s; __syncthreads();
    for (int o = 128; o > 0; o >>= 1) {
        if (tid < o) red[tid] += red[tid + o];
        __syncthreads();
    }
    const float inv = 1.f / red[0];
    for (int c = tid; c < Sc; c += 256)
        sc[c] = (c < lim) ? tf32r(expf(sc[c] - m) * inv) : 0.f;
}

__global__ void router_kernel(const float* __restrict__ rw) {
    const int tok  = blockIdx.x * 8 + (threadIdx.x >> 5);
    const int lane = threadIdx.x & 31;
    const float* tr = g_t2 + (size_t)tok * Hc;
    float acc[8];
#pragma unroll
    for (int e = 0; e < 8; e++) acc[e] = 0.f;
    for (int h = lane; h < Hc; h += 32) {
        const float tv = tr[h];
        const float* rp = rw + h * 8;
#pragma unroll
        for (int e = 0; e < 8; e++) acc[e] += tv * rp[e];
    }
#pragma unroll
    for (int e = 0; e < 8; e++)
        for (int o = 16; o; o >>= 1) acc[e] += __shfl_xor_sync(0xffffffffu, acc[e], o);
    if (lane == 0) {
        float m = acc[0];
        for (int e = 1; e < 8; e++) m = fmaxf(m, acc[e]);
        float p[8], s = 0.f;
        for (int e = 0; e < 8; e++) { p[e] = expf(acc[e] - m); s += p[e]; }
        for (int e = 0; e < 8; e++) p[e] /= s;
        bool used[8] = {false,false,false,false,false,false,false,false};
        int isel[4]; float wsel[4]; float tsum = 0.f;
        for (int kk = 0; kk < 4; kk++) {
            int best = 0; float bv = -1.f;
            for (int e = 0; e < 8; e++)
                if (!used[e] && p[e] > bv) { bv = p[e]; best = e; }
            used[best] = true; isel[kk] = best; wsel[kk] = bv; tsum += bv;
        }
        float outw[8] = {0,0,0,0,0,0,0,0};
        for (int kk = 0; kk < 4; kk++) outw[isel[kk]] = wsel[kk] / tsum;
        for (int e = 0; e < 8; e++) g_dw[tok * 8 + e] = outw[e];
        for (int kk = 0; kk < 4; kk++) {
            const int pos = atomicAdd(&g_cnt[isel[kk]], 1);
            g_list[isel[kk] * Tc + pos] = tok;
        }
    }
}

__global__ void moe_act_kernel() {
    const int e = blockIdx.z, row = blockIdx.y;
    if (row >= g_cnt[e]) return;
    const int col = blockIdx.x * 256 + threadIdx.x;
    if (col >= IM) return;
    const size_t i = ((size_t)e * Tc + row) * IM + col;
    const float g = g_mg[i], u = g_mu[i];
    g_mg[i] = tf32r(g / (1.f + expf(-g)) * u);
}

__global__ void shared_act_kernel() {
    const size_t i = (size_t)blockIdx.x * 256 + threadIdx.x;
    const float g = g_sgv[i], u = g_suv[i];
    g_sgv[i] = tf32r(g / (1.f + expf(-g)) * u);
}

__global__ void sgate_kernel(const float* __restrict__ sgw) {
    const int tok  = blockIdx.x * 8 + (threadIdx.x >> 5);
    const int lane = threadIdx.x & 31;
    const float* tr = g_t2 + (size_t)tok * Hc;
    float s = 0.f;
    for (int h = lane; h < Hc; h += 32) s += tr[h] * sgw[h];
    for (int o = 16; o; o >>= 1) s += __shfl_xor_sync(0xffffffffu, s, o);
    if (lane == 0) g_sgate[tok] = 1.f / (1.f + expf(-s));
}

__global__ void final_kernel(float* __restrict__ out) {
    const size_t i = (size_t)blockIdx.x * 256 + threadIdx.x;
    const int row = (int)(i >> 11);
    out[i] = g_x[i] + g_moe[i] + g_sgate[row] * g_sh[i];
}

// ---------------- tf32 GEMM: cp.async + ldmatrix, 64x64 warp tile ----------------
enum GMode { GM_Q, GM_K, GM_V, GM_SCORES, GM_PV, GM_O,
             GM_MG, GM_MU, GM_MD, GM_SG, GM_SU, GM_SD };

__device__ __forceinline__ void mma_tf32(float* c, const uint32_t* a, const uint32_t* b) {
    asm volatile(
        "mma.sync.aligned.m16n8k8.row.col.f32.tf32.tf32.f32 "
        "{%0,%1,%2,%3}, {%4,%5,%6,%7}, {%8,%9}, {%0,%1,%2,%3};"
        : "+f"(c[0]), "+f"(c[1]), "+f"(c[2]), "+f"(c[3])
        : "r"(a[0]), "r"(a[1]), "r"(a[2]), "r"(a[3]), "r"(b[0]), "r"(b[1]));
}

__device__ __forceinline__ void ldsm4(uint32_t& r0, uint32_t& r1, uint32_t& r2, uint32_t& r3,
                                      uint32_t addr) {
    asm volatile("ldmatrix.sync.aligned.m8n8.x4.shared.b16 {%0,%1,%2,%3}, [%4];"
                 : "=r"(r0), "=r"(r1), "=r"(r2), "=r"(r3) : "r"(addr));
}

__device__ __forceinline__ void cpa16(uint32_t dst, const void* src, int sz) {
    asm volatile("cp.async.cg.shared.global [%0], [%1], 16, %2;\n"
                 :: "r"(dst), "l"(src), "r"(sz));
}
__device__ __forceinline__ void cpa_commit() {
    asm volatile("cp.async.commit_group;\n");
}
__device__ __forceinline__ void cpa_wait0() {
    asm volatile("cp.async.wait_group 0;\n" ::: "memory");
}

constexpr int TST = 20;    // tile stride (floats): rows 0..7 at stride 20 cover all 32 banks

// BM=128, BN=128, BK=16; 128 threads = 4 warps (2x2), warp tile 64x64.
// A [m][k] and B [n][k] both k-major in smem; fragments via ldmatrix.x4.b16.
template<int MODE>
__global__ __launch_bounds__(128, 2) void gemm_kernel(const float* __restrict__ extra) {
    constexpr int Kv =
        (MODE==GM_SCORES) ? 128 :
        (MODE==GM_PV) ? Sc :
        (MODE==GM_MD) ? IM :
        (MODE==GM_SD) ? ISH : 2048;

    const int tid = threadIdx.x;
    const int z   = blockIdx.z;
    const int m0  = blockIdx.y * 128, n0 = blockIdx.x * 128;

    int Mz;
    if (MODE==GM_SCORES || MODE==GM_PV) Mz = Sc;
    else if (MODE==GM_MG || MODE==GM_MU || MODE==GM_MD) Mz = g_cnt[z];
    else Mz = Tc;
    if (m0 >= Mz) return;
    if (MODE==GM_SCORES && n0 > m0 + 127) return;   // fully masked tile

    int bb = 0, hh = 0;
    if (MODE==GM_SCORES || MODE==GM_PV) { bb = z >> 4; hh = z & 15; }

    // A: [m][k] row-major, lda; B: [n][k] row-major, ldb (= K stride)
    const float* A; const float* Bp; int lda, ldb;
    if (MODE==GM_Q) {
        A = g_h; lda = Hc; Bp = g_wr + OFF_WQ; ldb = 2048;
    } else if (MODE==GM_K) {
        A = g_h; lda = Hc; Bp = g_wr + OFF_WK; ldb = 2048;
    } else if (MODE==GM_V) {
        A = g_h; lda = Hc; Bp = g_wr + OFF_WV; ldb = 2048;
    } else if (MODE==GM_SCORES) {
        A = g_q + (size_t)bb * Sc * 2048 + hh * 128; lda = 2048;
        Bp = g_k + (size_t)bb * Sc * 256 + (hh >> 3) * 128; ldb = 256;
    } else if (MODE==GM_PV) {
        A = g_sc + (size_t)z * Sc * Sc; lda = Sc;
        Bp = g_vT + (size_t)(bb * 2 + (hh >> 3)) * 128 * Sc; ldb = Sc;
    } else if (MODE==GM_O) {
        A = g_ao; lda = 2048; Bp = g_wr + OFF_WO; ldb = 2048;
    } else if (MODE==GM_MG) {
        A = g_t2r; lda = 2048; Bp = g_wr + OFF_WG + (size_t)z * 2048 * IM; ldb = 2048;
    } else if (MODE==GM_MU) {
        A = g_t2r; lda = 2048; Bp = g_wr + OFF_WU + (size_t)z * 2048 * IM; ldb = 2048;
    } else if (MODE==GM_MD) {
        A = g_mg + (size_t)z * Tc * IM; lda = IM;
        Bp = g_wr + OFF_WD + (size_t)z * IM * 2048; ldb = IM;
    } else if (MODE==GM_SG) {
        A = g_t2r; lda = 2048; Bp = g_wr + OFF_SWG; ldb = 2048;
    } else if (MODE==GM_SU) {
        A = g_t2r; lda = 2048; Bp = g_wr + OFF_SWU; ldb = 2048;
    } else { // GM_SD
        A = g_sgv; lda = ISH; Bp = g_wr + OFF_SWD; ldb = ISH;
    }

    __shared__ float As[2][128][TST];   // [stage][m][k]
    __shared__ float Bs[2][128][TST];   // [stage][n][k]

    float acc[4][8][4];
#pragma unroll
    for (int i = 0; i < 4; i++)
#pragma unroll
        for (int j = 0; j < 8; j++)
#pragma unroll
            for (int r = 0; r < 4; r++) acc[i][j][r] = 0.f;

    const int lane = tid & 31, wid = tid >> 5;
    const int wm = (wid >> 1) * 64;
    const int wn = (wid & 1) * 64;

    // loaders: one row per thread (A row m0+tid, B row n0+tid)
    const int lm = tid;
    const int agl = m0 + lm;
    const bool aval = agl < Mz;
    const float* arp;
    if (MODE==GM_MG || MODE==GM_MU)
        arp = A + (size_t)(aval ? g_list[z * Tc + agl] : 0) * lda;
    else
        arp = A + (size_t)(aval ? agl : 0) * lda;
    const int asz = aval ? 16 : 0;
    const float* brp = Bp + (size_t)(n0 + lm) * ldb;
    const int rot = (lm >> 3) & 3;    // chunk rotation -> conflict-free cp.async stores

    const int Kend = (MODE==GM_PV) ? (m0 + 128) : Kv;
    const int nt = Kend / 16;

    uint32_t sA[2], sB[2];
    sA[0] = (uint32_t)__cvta_generic_to_shared(&As[0][0][0]);
    sA[1] = (uint32_t)__cvta_generic_to_shared(&As[1][0][0]);
    sB[0] = (uint32_t)__cvta_generic_to_shared(&Bs[0][0][0]);
    sB[1] = (uint32_t)__cvta_generic_to_shared(&Bs[1][0][0]);

    auto load_stage = [&](int s, int k0) {
#pragma unroll
        for (int c = 0; c < 4; c++) {
            const int cc = (c + rot) & 3;
            cpa16(sA[s] + (uint32_t)(lm * TST + cc * 4) * 4, arp + k0 + cc * 4, asz);
        }
#pragma unroll
        for (int c = 0; c < 4; c++) {
            const int cc = (c + rot) & 3;
            cpa16(sB[s] + (uint32_t)(lm * TST + cc * 4) * 4, brp + k0 + cc * 4, 16);
        }
    };

    load_stage(0, 0);
    cpa_commit();

    // ldmatrix addressing: row = base + (lane & 15), col chunk = klo + ((lane>>4)*4)
    const int lrow = lane & 15;
    const int lcol = (lane >> 4) << 2;

    for (int t = 0; t < nt; t++) {
        cpa_wait0();
        __syncthreads();
        if (t + 1 < nt) { load_stage((t + 1) & 1, (t + 1) * 16); }
        cpa_commit();

        const int buf = t & 1;
#pragma unroll
        for (int ks = 0; ks < 2; ks++) {
            const int klo = ks * 8;
            uint32_t af[4][4], bf[8][2];
#pragma unroll
            for (int i = 0; i < 4; i++) {
                const uint32_t addr = sA[buf] +
                    (uint32_t)((wm + i * 16 + lrow) * TST + klo + lcol) * 4;
                ldsm4(af[i][0], af[i][1], af[i][2], af[i][3], addr);
            }
#pragma unroll
            for (int jj = 0; jj < 4; jj++) {
                const uint32_t addr = sB[buf] +
                    (uint32_t)((wn + jj * 16 + lrow) * TST + klo + lcol) * 4;
                uint32_t r0, r1, r2, r3;
                ldsm4(r0, r1, r2, r3, addr);
                bf[2*jj][0] = r0; bf[2*jj][1] = r2;
                bf[2*jj+1][0] = r1; bf[2*jj+1][1] = r3;
            }
#pragma unroll
            for (int i = 0; i < 4; i++)
#pragma unroll
                for (int j = 0; j < 8; j++)
                    mma_tf32(acc[i][j], af[i], bf[j]);
        }
        __syncthreads();
    }

    // ---------------- epilogues ----------------
    const float scl = 0.08838834764831845f;  // 1/sqrt(128)
    constexpr bool RND = (MODE==GM_V || MODE==GM_PV);
#pragma unroll
    for (int i = 0; i < 4; i++) {
#pragma unroll
        for (int rr = 0; rr < 2; rr++) {
            const int r = m0 + wm + i * 16 + (lane >> 2) + rr * 8;
            if (r >= Mz) continue;
            if (MODE==GM_SCORES) {
                const size_t base = (size_t)z * Sc * Sc + (size_t)r * Sc;
#pragma unroll
                for (int j = 0; j < 8; j++) {
                    const int c = n0 + wn + j * 8 + (lane & 3) * 2;
                    float v0 = acc[i][j][rr * 2 + 0] * scl;
                    float v1 = acc[i][j][rr * 2 + 1] * scl;
                    if (c > r)     v0 = -1e9f;
                    if (c + 1 > r) v1 = -1e9f;
                    g_sc[base + c]     = v0;
                    g_sc[base + c + 1] = v1;
                }
            } else if (MODE==GM_MD) {
                const int tok = g_list[z * Tc + r];
                const float w = g_dw[tok * Ec + z];
                float* dst = g_moe + (size_t)tok * 2048;
#pragma unroll
                for (int j = 0; j < 8; j++) {
                    const int c = n0 + wn + j * 8 + (lane & 3) * 2;
                    atomicAdd(dst + c,     acc[i][j][rr * 2 + 0] * w);
                    atomicAdd(dst + c + 1, acc[i][j][rr * 2 + 1] * w);
                }
            } else {
                float* Cp; int ldc; const float* bias = nullptr; const float* res = nullptr;
                if (MODE==GM_Q)       { Cp = g_q;  ldc = 2048; bias = extra; }
                else if (MODE==GM_K)  { Cp = g_k;  ldc = 256;  bias = extra; }
                else if (MODE==GM_V)  { Cp = g_v;  ldc = 256;  bias = extra; }
                else if (MODE==GM_PV) { Cp = g_ao + (size_t)bb * Sc * 2048 + hh * 128; ldc = 2048; }
                else if (MODE==GM_O)  { Cp = g_x;  ldc = 2048; res = extra; }
                else if (MODE==GM_MG) { Cp = g_mg + (size_t)z * Tc * IM; ldc = IM; }
                else if (MODE==GM_MU) { Cp = g_mu + (size_t)z * Tc * IM; ldc = IM; }
                else if (MODE==GM_SG) { Cp = g_sgv; ldc = ISH; }
                else if (MODE==GM_SU) { Cp = g_suv; ldc = ISH; }
                else                  { Cp = g_sh;  ldc = 2048; }
                const size_t rowoff = (size_t)r * ldc;
#pragma unroll
                for (int j = 0; j < 8; j++) {
                    const int c = n0 + wn + j * 8 + (lane & 3) * 2;
                    float v0 = acc[i][j][rr * 2 + 0];
                    float v1 = acc[i][j][rr * 2 + 1];
                    if (bias) { v0 += bias[c]; v1 += bias[c + 1]; }
                    if (res)  { v0 += res[rowoff + c]; v1 += res[rowoff + c + 1]; }
                    if (RND)  { v0 = tf32r(v0); v1 = tf32r(v1); }
                    Cp[rowoff + c]     = v0;
                    Cp[rowoff + c + 1] = v1;
                }
            }
        }
    }
}

// ---------------- launch ----------------
extern "C" void kernel_launch(void* const* d_in, const int* in_sizes, int n_in,
                              void* d_out, int out_size) {
    (void)in_sizes; (void)n_in; (void)out_size;
    const float* x0  = (const float*)d_in[0];
    const float* ln1 = (const float*)d_in[1];
    const float* wq  = (const float*)d_in[2];
    const float* bq  = (const float*)d_in[3];
    const float* wk  = (const float*)d_in[4];
    const float* bk  = (const float*)d_in[5];
    const float* wv  = (const float*)d_in[6];
    const float* bv  = (const float*)d_in[7];
    const float* wo  = (const float*)d_in[8];
    const float* ln2 = (const float*)d_in[9];
    const float* rw  = (const float*)d_in[10];
    const float* wg  = (const float*)d_in[11];
    const float* wu  = (const float*)d_in[12];
    const float* wd  = (const float*)d_in[13];
    const float* swg = (const float*)d_in[14];
    const float* swu = (const float*)d_in[15];
    const float* swd = (const float*)d_in[16];
    const float* sgw = (const float*)d_in[17];
    float* out = (float*)d_out;

    const dim3 tb(32, 8);
    // rounded transposes: dst[n][k] = tf32r(src[k][n]); grid (N/32, K/32, E)
    round_tr_kernel<<<dim3(2048/32, 2048/32, 1), tb>>>(wq,  OFF_WQ,  2048, 2048);
    round_tr_kernel<<<dim3(256/32,  2048/32, 1), tb>>>(wk,  OFF_WK,  2048, 256);
    round_tr_kernel<<<dim3(256/32,  2048/32, 1), tb>>>(wv,  OFF_WV,  2048, 256);
    round_tr_kernel<<<dim3(2048/32, 2048/32, 1), tb>>>(wo,  OFF_WO,  2048, 2048);
    round_tr_kernel<<<dim3(IM/32,   2048/32, Ec), tb>>>(wg,  OFF_WG,  2048, IM);
    round_tr_kernel<<<dim3(IM/32,   2048/32, Ec), tb>>>(wu,  OFF_WU,  2048, IM);
    round_tr_kernel<<<dim3(2048/32, IM/32,   Ec), tb>>>(wd,  OFF_WD,  IM,   2048);
    round_tr_kernel<<<dim3(ISH/32,  2048/32, 1), tb>>>(swg, OFF_SWG, 2048, ISH);
    round_tr_kernel<<<dim3(ISH/32,  2048/32, 1), tb>>>(swu, OFF_SWU, 2048, ISH);
    round_tr_kernel<<<dim3(2048/32, ISH/32,  1), tb>>>(swd, OFF_SWD, ISH,  2048);

    clear_cnt_kernel<<<1, 32>>>();
    clear_moe_kernel<<<(Tc * Hc) / 256, 256>>>();

    // attention
    rmsnorm_kernel<0><<<Tc, 256>>>(x0, ln1);
    gemm_kernel<GM_Q><<<dim3(16, 32, 1), 128>>>(bq);
    gemm_kernel<GM_K><<<dim3(2, 32, 1), 128>>>(bk);
    gemm_kernel<GM_V><<<dim3(2, 32, 1), 128>>>(bv);
    rope_kernel<<<dim3(Tc, NQc + NKVc), 64>>>();
    vT_kernel<<<(Bc * NKVc * DHc * Sc) / 256, 256>>>();
    gemm_kernel<GM_SCORES><<<dim3(16, 16, 32), 128>>>(nullptr);
    softmax_kernel<<<Bc * NQc * Sc, 256>>>();
    gemm_kernel<GM_PV><<<dim3(1, 16, 32), 128>>>(nullptr);
    gemm_kernel<GM_O><<<dim3(16, 32, 1), 128>>>(x0);

    // MoE block
    rmsnorm_kernel<1><<<Tc, 256>>>(nullptr, ln2);
    router_kernel<<<Tc / 8, 256>>>(rw);
    gemm_kernel<GM_MG><<<dim3(11, 32, 8), 128>>>(nullptr);
    gemm_kernel<GM_MU><<<dim3(11, 32, 8), 128>>>(nullptr);
    moe_act_kernel<<<dim3(6, Tc, 8), 256>>>();
    gemm_kernel<GM_MD><<<dim3(16, 32, 8), 128>>>(nullptr);

    // shared expert
    gemm_kernel<GM_SG><<<dim3(44, 32, 1), 128>>>(nullptr);
    gemm_kernel<GM_SU><<<dim3(44, 32, 1), 128>>>(nullptr);
    shared_act_kernel<<<(size_t)(Tc) * ISH / 256, 256>>>();
    sgate_kernel<<<Tc / 8, 256>>>(sgw);
    gemm_kernel<GM_SD><<<dim3(16, 32, 1), 128>>>(nullptr);

    final_kernel<<<(Tc * Hc) / 256, 256>>>(out);
}

// round 8
// speedup vs baseline: 1.3897x; 1.3897x over previous
#include <cuda_runtime.h>
#include <math.h>
#include <stdint.h>

// ---------------- problem constants ----------------
constexpr int Bc   = 2;
constexpr int Sc   = 2048;
constexpr int Hc   = 2048;
constexpr int Tc   = Bc * Sc;      // 4096 tokens
constexpr int Ec   = 8;
constexpr int IM   = 1408;
constexpr int ISH  = 5632;
constexpr int NQc  = 16;
constexpr int NKVc = 2;
constexpr int DHc  = 128;
constexpr float EPSc = 1e-5f;

// rounded-weight scratch offsets (original [k][n] layout)
constexpr size_t OFF_WQ  = 0;
constexpr size_t OFF_WK  = OFF_WQ  + (size_t)2048 * 2048;
constexpr size_t OFF_WV  = OFF_WK  + (size_t)2048 * 256;
constexpr size_t OFF_WO  = OFF_WV  + (size_t)2048 * 256;
constexpr size_t OFF_WG  = OFF_WO  + (size_t)2048 * 2048;
constexpr size_t OFF_WU  = OFF_WG  + (size_t)Ec * 2048 * IM;
constexpr size_t OFF_WD  = OFF_WU  + (size_t)Ec * 2048 * IM;
constexpr size_t OFF_SWG = OFF_WD  + (size_t)Ec * IM * 2048;
constexpr size_t OFF_SWU = OFF_SWG + (size_t)2048 * ISH;
constexpr size_t OFF_SWD = OFF_SWU + (size_t)2048 * ISH;
constexpr size_t WR_TOT  = OFF_SWD + (size_t)ISH * 2048;

// ---------------- scratch (device globals; no allocations allowed) ----------------
__device__ float g_wr [WR_TOT];                      // tf32-rounded weights
__device__ float g_h  [(size_t)Tc * Hc];
__device__ float g_q  [(size_t)Tc * NQc * DHc];
__device__ float g_k  [(size_t)Tc * NKVc * DHc];
__device__ float g_v  [(size_t)Tc * NKVc * DHc];
__device__ float g_kT [(size_t)Bc * NKVc * DHc * Sc];
__device__ float g_sc [(size_t)Bc * NQc * Sc * Sc];  // scores -> probs in place
__device__ float g_ao [(size_t)Tc * Hc];
__device__ float g_x  [(size_t)Tc * Hc];
__device__ float g_t2 [(size_t)Tc * Hc];             // exact (router/sgate)
__device__ float g_t2r[(size_t)Tc * Hc];             // tf32-rounded (GEMM A)
__device__ float g_dw [Tc * Ec];
__device__ int   g_cnt[Ec];
__device__ int   g_list[Ec * Tc];
__device__ float g_mg [(size_t)Ec * Tc * IM];
__device__ float g_mu [(size_t)Ec * Tc * IM];
__device__ float g_moe[(size_t)Tc * Hc];
__device__ float g_sgv[(size_t)Tc * ISH];
__device__ float g_suv[(size_t)Tc * ISH];
__device__ float g_sh [(size_t)Tc * Hc];
__device__ float g_sgate[Tc];

__device__ __forceinline__ float tf32r(float x) {
    uint32_t u;
    asm("cvt.rna.tf32.f32 %0, %1;" : "=r"(u) : "f"(x));
    return __uint_as_float(u);
}

// ---------------- weight rounding ----------------
template<size_t OFF>
__global__ void round_copy_kernel(const float* __restrict__ src, int n) {
    const int i = blockIdx.x * 256 + threadIdx.x;
    if (i < n) g_wr[OFF + i] = tf32r(src[i]);
}

// ---------------- small kernels ----------------
__global__ void clear_cnt_kernel() {
    if (threadIdx.x < Ec) g_cnt[threadIdx.x] = 0;
}
__global__ void clear_moe_kernel() {
    g_moe[(size_t)blockIdx.x * 256 + threadIdx.x] = 0.f;
}

template<int PHASE>
__global__ void rmsnorm_kernel(const float* __restrict__ xin,
                               const float* __restrict__ scale) {
    __shared__ float red[256];
    const int row = blockIdx.x;
    const float* x = (PHASE == 0) ? (xin + (size_t)row * Hc) : (g_x + (size_t)row * Hc);
    float s = 0.f;
    for (int i = threadIdx.x; i < Hc; i += 256) { float v = x[i]; s += v * v; }
    red[threadIdx.x] = s; __syncthreads();
    for (int o = 128; o > 0; o >>= 1) {
        if (threadIdx.x < o) red[threadIdx.x] += red[threadIdx.x + o];
        __syncthreads();
    }
    const float inv = rsqrtf(red[0] / (float)Hc + EPSc);
    for (int i = threadIdx.x; i < Hc; i += 256) {
        const float v = x[i] * inv * scale[i];
        if (PHASE == 0) {
            g_h[(size_t)row * Hc + i] = tf32r(v);
        } else {
            g_t2 [(size_t)row * Hc + i] = v;
            g_t2r[(size_t)row * Hc + i] = tf32r(v);
        }
    }
}

__global__ void rope_kernel() {
    const int tok  = blockIdx.x;
    const int head = blockIdx.y;
    const int j    = threadIdx.x;         // 0..63
    const int s    = tok & (Sc - 1);
    const float inv = powf(10000.f, -(float)(2 * j) / 128.f);
    const float ang = (float)s * inv;
    float si, c;
    sincosf(ang, &si, &c);
    float* p = (head < NQc) ? (g_q + (size_t)tok * (NQc * DHc) + head * DHc)
                            : (g_k + (size_t)tok * (NKVc * DHc) + (head - NQc) * DHc);
    const float x1 = p[j], x2 = p[j + 64];
    p[j]      = tf32r(x1 * c - x2 * si);
    p[j + 64] = tf32r(x2 * c + x1 * si);
}

__global__ void kT_kernel() {
    const int i  = blockIdx.x * 256 + threadIdx.x;
    const int s  = i & (Sc - 1);
    const int d  = (i >> 11) & 127;
    const int bk = i >> 18;
    g_kT[i] = g_k[((size_t)((bk >> 1) * Sc + s)) * (NKVc * DHc) + (bk & 1) * DHc + d];
}

// single-pass register-resident causal softmax; one read, one exp, one write
__global__ void softmax_kernel() {
    __shared__ float red[256];
    const size_t rid = blockIdx.x;
    const int r   = (int)(rid & (Sc - 1));
    float* sc = g_sc + rid * Sc;
    const int lim = r + 1;
    const int nf4 = (lim + 3) >> 2;       // float4's that contain live data
    const int tid = threadIdx.x;

    float4 v4[2];
    float m = -1e30f;
#pragma unroll
    for (int s4 = 0; s4 < 2; s4++) {
        const int j = tid + s4 * 256;
        if (j < nf4) {
            float4 v = *(const float4*)(sc + j * 4);
            const int c0 = j * 4;
            if (c0 + 0 >= lim) v.x = -1e30f;
            if (c0 + 1 >= lim) v.y = -1e30f;
            if (c0 + 2 >= lim) v.z = -1e30f;
            if (c0 + 3 >= lim) v.w = -1e30f;
            v4[s4] = v;
            m = fmaxf(m, fmaxf(fmaxf(v.x, v.y), fmaxf(v.z, v.w)));
        } else {
            v4[s4] = make_float4(-1e30f, -1e30f, -1e30f, -1e30f);
        }
    }
    red[tid] = m; __syncthreads();
    for (int o = 128; o > 0; o >>= 1) {
        if (tid < o) red[tid] = fmaxf(red[tid], red[tid + o]);
        __syncthreads();
    }
    m = red[0]; __syncthreads();

    float s = 0.f;
#pragma unroll
    for (int s4 = 0; s4 < 2; s4++) {
        float4& v = v4[s4];
        v.x = (v.x > -1e29f) ? expf(v.x - m) : 0.f;
        v.y = (v.y > -1e29f) ? expf(v.y - m) : 0.f;
        v.z = (v.z > -1e29f) ? expf(v.z - m) : 0.f;
        v.w = (v.w > -1e29f) ? expf(v.w - m) : 0.f;
        s += v.x + v.y + v.z + v.w;
    }
    red[tid] = s; __syncthreads();
    for (int o = 128; o > 0; o >>= 1) {
        if (tid < o) red[tid] += red[tid + o];
        __syncthreads();
    }
    const float inv = 1.f / red[0];

#pragma unroll
    for (int s4 = 0; s4 < 2; s4++) {
        const int j = tid + s4 * 256;
        float4 o4;
        const float4 v = v4[s4];
        o4.x = tf32r(v.x * inv); o4.y = tf32r(v.y * inv);
        o4.z = tf32r(v.z * inv); o4.w = tf32r(v.w * inv);
        *(float4*)(sc + j * 4) = o4;   // j >= nf4 writes exact zeros
    }
}

__global__ void router_kernel(const float* __restrict__ rw) {
    const int tok  = blockIdx.x * 8 + (threadIdx.x >> 5);
    const int lane = threadIdx.x & 31;
    const float* tr = g_t2 + (size_t)tok * Hc;
    float acc[8];
#pragma unroll
    for (int e = 0; e < 8; e++) acc[e] = 0.f;
    for (int h = lane; h < Hc; h += 32) {
        const float tv = tr[h];
        const float* rp = rw + h * 8;
#pragma unroll
        for (int e = 0; e < 8; e++) acc[e] += tv * rp[e];
    }
#pragma unroll
    for (int e = 0; e < 8; e++)
        for (int o = 16; o; o >>= 1) acc[e] += __shfl_xor_sync(0xffffffffu, acc[e], o);
    if (lane == 0) {
        float m = acc[0];
        for (int e = 1; e < 8; e++) m = fmaxf(m, acc[e]);
        float p[8], s = 0.f;
        for (int e = 0; e < 8; e++) { p[e] = expf(acc[e] - m); s += p[e]; }
        for (int e = 0; e < 8; e++) p[e] /= s;
        bool used[8] = {false,false,false,false,false,false,false,false};
        int isel[4]; float wsel[4]; float tsum = 0.f;
        for (int kk = 0; kk < 4; kk++) {
            int best = 0; float bv = -1.f;
            for (int e = 0; e < 8; e++)
                if (!used[e] && p[e] > bv) { bv = p[e]; best = e; }
            used[best] = true; isel[kk] = best; wsel[kk] = bv; tsum += bv;
        }
        float outw[8] = {0,0,0,0,0,0,0,0};
        for (int kk = 0; kk < 4; kk++) outw[isel[kk]] = wsel[kk] / tsum;
        for (int e = 0; e < 8; e++) g_dw[tok * 8 + e] = outw[e];
        for (int kk = 0; kk < 4; kk++) {
            const int pos = atomicAdd(&g_cnt[isel[kk]], 1);
            g_list[isel[kk] * Tc + pos] = tok;
        }
    }
}

__global__ void moe_act_kernel() {
    const int e = blockIdx.z, row = blockIdx.y;
    if (row >= g_cnt[e]) return;
    const int col = blockIdx.x * 256 + threadIdx.x;
    if (col >= IM) return;
    const size_t i = ((size_t)e * Tc + row) * IM + col;
    const float g = g_mg[i], u = g_mu[i];
    g_mg[i] = tf32r(g / (1.f + expf(-g)) * u);
}

__global__ void shared_act_kernel() {
    const size_t i = (size_t)blockIdx.x * 256 + threadIdx.x;
    const float g = g_sgv[i], u = g_suv[i];
    g_sgv[i] = tf32r(g / (1.f + expf(-g)) * u);
}

__global__ void sgate_kernel(const float* __restrict__ sgw) {
    const int tok  = blockIdx.x * 8 + (threadIdx.x >> 5);
    const int lane = threadIdx.x & 31;
    const float* tr = g_t2 + (size_t)tok * Hc;
    float s = 0.f;
    for (int h = lane; h < Hc; h += 32) s += tr[h] * sgw[h];
    for (int o = 16; o; o >>= 1) s += __shfl_xor_sync(0xffffffffu, s, o);
    if (lane == 0) g_sgate[tok] = 1.f / (1.f + expf(-s));
}

__global__ void final_kernel(float* __restrict__ out) {
    const size_t i = (size_t)blockIdx.x * 256 + threadIdx.x;
    const int row = (int)(i >> 11);
    out[i] = g_x[i] + g_moe[i] + g_sgate[row] * g_sh[i];
}

// ---------------- tf32 GEMM: cp.async + ldmatrix-A, 64x64 warp tile ----------------
enum GMode { GM_Q, GM_K, GM_V, GM_SCORES, GM_PV, GM_O,
             GM_MG, GM_MU, GM_MD, GM_SG, GM_SU, GM_SD };

__device__ __forceinline__ void mma_tf32(float* c, const uint32_t* a, const uint32_t* b) {
    asm volatile(
        "mma.sync.aligned.m16n8k8.row.col.f32.tf32.tf32.f32 "
        "{%0,%1,%2,%3}, {%4,%5,%6,%7}, {%8,%9}, {%0,%1,%2,%3};"
        : "+f"(c[0]), "+f"(c[1]), "+f"(c[2]), "+f"(c[3])
        : "r"(a[0]), "r"(a[1]), "r"(a[2]), "r"(a[3]), "r"(b[0]), "r"(b[1]));
}

__device__ __forceinline__ void ldsm4(uint32_t& r0, uint32_t& r1, uint32_t& r2, uint32_t& r3,
                                      uint32_t addr) {
    asm volatile("ldmatrix.sync.aligned.m8n8.x4.shared.b16 {%0,%1,%2,%3}, [%4];"
                 : "=r"(r0), "=r"(r1), "=r"(r2), "=r"(r3) : "r"(addr));
}

__device__ __forceinline__ void cpa16(uint32_t dst, const void* src, int sz) {
    asm volatile("cp.async.cg.shared.global [%0], [%1], 16, %2;\n"
                 :: "r"(dst), "l"(src), "r"(sz));
}
__device__ __forceinline__ void cpa_commit() {
    asm volatile("cp.async.commit_group;\n");
}
__device__ __forceinline__ void cpa_wait0() {
    asm volatile("cp.async.wait_group 0;\n" ::: "memory");
}

constexpr int AST = 20;    // As stride (floats): conflict-free LDSM + cp.async
constexpr int BST = 136;   // Bs stride (floats)

// BM=128, BN=128, BK=16; 128 threads = 4 warps (2x2), warp tile 64x64.
template<int MODE>
__global__ __launch_bounds__(128, 2) void gemm_kernel(const float* __restrict__ extra) {
    constexpr int Kv =
        (MODE==GM_SCORES) ? 128 :
        (MODE==GM_PV) ? Sc :
        (MODE==GM_MD) ? IM :
        (MODE==GM_SD) ? ISH : 2048;

    const int tid = threadIdx.x;
    const int z   = blockIdx.z;
    const int m0  = blockIdx.y * 128, n0 = blockIdx.x * 128;

    int Mz;
    if (MODE==GM_SCORES || MODE==GM_PV) Mz = Sc;
    else if (MODE==GM_MG || MODE==GM_MU || MODE==GM_MD) Mz = g_cnt[z];
    else Mz = Tc;
    if (m0 >= Mz) return;
    if (MODE==GM_SCORES && n0 > m0 + 127) return;   // fully masked tile

    int bb = 0, hh = 0;
    if (MODE==GM_SCORES || MODE==GM_PV) { bb = z >> 4; hh = z & 15; }

    const float* A; const float* Bp; int lda, ldb;
    if (MODE==GM_Q) {
        A = g_h; lda = Hc; Bp = g_wr + OFF_WQ; ldb = 2048;
    } else if (MODE==GM_K) {
        A = g_h; lda = Hc; Bp = g_wr + OFF_WK; ldb = 256;
    } else if (MODE==GM_V) {
        A = g_h; lda = Hc; Bp = g_wr + OFF_WV; ldb = 256;
    } else if (MODE==GM_SCORES) {
        A = g_q + (size_t)bb * Sc * 2048 + hh * 128; lda = 2048;
        Bp = g_kT + (size_t)(bb * 2 + (hh >> 3)) * 128 * Sc; ldb = Sc;
    } else if (MODE==GM_PV) {
        A = g_sc + (size_t)z * Sc * Sc; lda = Sc;
        Bp = g_v + (size_t)bb * Sc * 256 + (hh >> 3) * 128; ldb = 256;
    } else if (MODE==GM_O) {
        A = g_ao; lda = 2048; Bp = g_wr + OFF_WO; ldb = 2048;
    } else if (MODE==GM_MG) {
        A = g_t2r; lda = 2048; Bp = g_wr + OFF_WG + (size_t)z * 2048 * IM; ldb = IM;
    } else if (MODE==GM_MU) {
        A = g_t2r; lda = 2048; Bp = g_wr + OFF_WU + (size_t)z * 2048 * IM; ldb = IM;
    } else if (MODE==GM_MD) {
        A = g_mg + (size_t)z * Tc * IM; lda = IM;
        Bp = g_wr + OFF_WD + (size_t)z * IM * 2048; ldb = 2048;
    } else if (MODE==GM_SG) {
        A = g_t2r; lda = 2048; Bp = g_wr + OFF_SWG; ldb = ISH;
    } else if (MODE==GM_SU) {
        A = g_t2r; lda = 2048; Bp = g_wr + OFF_SWU; ldb = ISH;
    } else { // GM_SD
        A = g_sgv; lda = ISH; Bp = g_wr + OFF_SWD; ldb = 2048;
    }

    __shared__ float As[2][128][AST];   // [stage][m][k]
    __shared__ float Bs[2][16][BST];    // [stage][k][n]

    float acc[4][8][4];
#pragma unroll
    for (int i = 0; i < 4; i++)
#pragma unroll
        for (int j = 0; j < 8; j++)
#pragma unroll
            for (int r = 0; r < 4; r++) acc[i][j][r] = 0.f;

    const int lane = tid & 31, wid = tid >> 5;
    const int wm = (wid >> 1) * 64;
    const int wn = (wid & 1) * 64;

    // A loader: one row per thread
    const int lm = tid;
    const int agl = m0 + lm;
    const bool aval = agl < Mz;
    const float* arp;
    if (MODE==GM_MG || MODE==GM_MU)
        arp = A + (size_t)(aval ? g_list[z * Tc + agl] : 0) * lda;
    else
        arp = A + (size_t)(aval ? agl : 0) * lda;
    const int asz = aval ? 16 : 0;
    const int arot = (lm >> 3) & 3;   // chunk rotation -> conflict-free cp.async stores

    // B loader: per warp one k-row per chunk, 128 cols split across lanes
    const int bw = tid >> 5;          // k sub-row
    const int bn = (tid & 31) * 4;
    const float* bbase = Bp + n0;

    const int Kend = (MODE==GM_PV) ? (m0 + 128) : Kv;
    const int nt = Kend / 16;

    uint32_t sA[2], sB[2];
    sA[0] = (uint32_t)__cvta_generic_to_shared(&As[0][0][0]);
    sA[1] = (uint32_t)__cvta_generic_to_shared(&As[1][0][0]);
    sB[0] = (uint32_t)__cvta_generic_to_shared(&Bs[0][0][0]);
    sB[1] = (uint32_t)__cvta_generic_to_shared(&Bs[1][0][0]);

    auto load_stage = [&](int s, int k0) {
#pragma unroll
        for (int c = 0; c < 4; c++) {
            const int cc = (c + arot) & 3;
            cpa16(sA[s] + (uint32_t)(lm * AST + cc * 4) * 4, arp + k0 + cc * 4, asz);
        }
#pragma unroll
        for (int c = 0; c < 4; c++) {
            const int k = c * 4 + bw;
            cpa16(sB[s] + (uint32_t)(k * BST + bn) * 4,
                  bbase + (size_t)(k0 + k) * ldb + bn, 16);
        }
    };

    load_stage(0, 0);
    cpa_commit();

    const int cb = wn + (lane >> 2);
    const int kq = lane & 3;
    const int lrow = lane & 15;            // ldmatrix source row within 16-row group
    const int lcol = (lane >> 4) << 2;     // 0 or 4: k sub-chunk

    for (int t = 0; t < nt; t++) {
        cpa_wait0();
        __syncthreads();
        if (t + 1 < nt) load_stage((t + 1) & 1, (t + 1) * 16);
        cpa_commit();

        const int buf = t & 1;
#pragma unroll
        for (int ks = 0; ks < 2; ks++) {
            const int klo = ks * 8;
            const int kk = klo + kq;
            uint32_t af[4][4], bf[8][2];
#pragma unroll
            for (int i = 0; i < 4; i++) {
                const uint32_t addr = sA[buf] +
                    (uint32_t)((wm + i * 16 + lrow) * AST + klo + lcol) * 4;
                ldsm4(af[i][0], af[i][1], af[i][2], af[i][3], addr);
            }
#pragma unroll
            for (int j = 0; j < 8; j++) {
                bf[j][0] = __float_as_uint(Bs[buf][kk][cb + j * 8]);
                bf[j][1] = __float_as_uint(Bs[buf][kk + 4][cb + j * 8]);
            }
#pragma unroll
            for (int i = 0; i < 4; i++)
#pragma unroll
                for (int j = 0; j < 8; j++)
                    mma_tf32(acc[i][j], af[i], bf[j]);
        }
        __syncthreads();
    }

    // ---------------- epilogues ----------------
    const float scl = 0.08838834764831845f;  // 1/sqrt(128)
    constexpr bool RND = (MODE==GM_V || MODE==GM_PV);
#pragma unroll
    for (int i = 0; i < 4; i++) {
#pragma unroll
        for (int rr = 0; rr < 2; rr++) {
            const int r = m0 + wm + i * 16 + (lane >> 2) + rr * 8;
            if (r >= Mz) continue;
            if (MODE==GM_SCORES) {
                const size_t base = (size_t)z * Sc * Sc + (size_t)r * Sc;
#pragma unroll
                for (int j = 0; j < 8; j++) {
                    const int c = n0 + wn + j * 8 + (lane & 3) * 2;
                    float v0 = acc[i][j][rr * 2 + 0] * scl;
                    float v1 = acc[i][j][rr * 2 + 1] * scl;
                    if (c > r)     v0 = -1e9f;
                    if (c + 1 > r) v1 = -1e9f;
                    g_sc[base + c]     = v0;
                    g_sc[base + c + 1] = v1;
                }
            } else if (MODE==GM_MD) {
                const int tok = g_list[z * Tc + r];
                const float w = g_dw[tok * Ec + z];
                float* dst = g_moe + (size_t)tok * 2048;
#pragma unroll
                for (int j = 0; j < 8; j++) {
                    const int c = n0 + wn + j * 8 + (lane & 3) * 2;
                    atomicAdd(dst + c,     acc[i][j][rr * 2 + 0] * w);
                    atomicAdd(dst + c + 1, acc[i][j][rr * 2 + 1] * w);
                }
            } else {
                float* Cp; int ldc; const float* bias = nullptr; const float* res = nullptr;
                if (MODE==GM_Q)       { Cp = g_q;  ldc = 2048; bias = extra; }
                else if (MODE==GM_K)  { Cp = g_k;  ldc = 256;  bias = extra; }
                else if (MODE==GM_V)  { Cp = g_v;  ldc = 256;  bias = extra; }
                else if (MODE==GM_PV) { Cp = g_ao + (size_t)bb * Sc * 2048 + hh * 128; ldc = 2048; }
                else if (MODE==GM_O)  { Cp = g_x;  ldc = 2048; res = extra; }
                else if (MODE==GM_MG) { Cp = g_mg + (size_t)z * Tc * IM; ldc = IM; }
                else if (MODE==GM_MU) { Cp = g_mu + (size_t)z * Tc * IM; ldc = IM; }
                else if (MODE==GM_SG) { Cp = g_sgv; ldc = ISH; }
                else if (MODE==GM_SU) { Cp = g_suv; ldc = ISH; }
                else                  { Cp = g_sh;  ldc = 2048; }
                const size_t rowoff = (size_t)r * ldc;
#pragma unroll
                for (int j = 0; j < 8; j++) {
                    const int c = n0 + wn + j * 8 + (lane & 3) * 2;
                    float v0 = acc[i][j][rr * 2 + 0];
                    float v1 = acc[i][j][rr * 2 + 1];
                    if (bias) { v0 += bias[c]; v1 += bias[c + 1]; }
                    if (res)  { v0 += res[rowoff + c]; v1 += res[rowoff + c + 1]; }
                    if (RND)  { v0 = tf32r(v0); v1 = tf32r(v1); }
                    Cp[rowoff + c]     = v0;
                    Cp[rowoff + c + 1] = v1;
                }
            }
        }
    }
}

// ---------------- launch ----------------
extern "C" void kernel_launch(void* const* d_in, const int* in_sizes, int n_in,
                              void* d_out, int out_size) {
    (void)in_sizes; (void)n_in; (void)out_size;
    const float* x0  = (const float*)d_in[0];
    const float* ln1 = (const float*)d_in[1];
    const float* wq  = (const float*)d_in[2];
    const float* bq  = (const float*)d_in[3];
    const float* wk  = (const float*)d_in[4];
    const float* bk  = (const float*)d_in[5];
    const float* wv  = (const float*)d_in[6];
    const float* bv  = (const float*)d_in[7];
    const float* wo  = (const float*)d_in[8];
    const float* ln2 = (const float*)d_in[9];
    const float* rw  = (const float*)d_in[10];
    const float* wg  = (const float*)d_in[11];
    const float* wu  = (const float*)d_in[12];
    const float* wd  = (const float*)d_in[13];
    const float* swg = (const float*)d_in[14];
    const float* swu = (const float*)d_in[15];
    const float* swd = (const float*)d_in[16];
    const float* sgw = (const float*)d_in[17];
    float* out = (float*)d_out;

    auto blocks = [](size_t n) { return (unsigned)((n + 255) / 256); };

    round_copy_kernel<OFF_WQ ><<<blocks((size_t)2048*2048), 256>>>(wq,  2048*2048);
    round_copy_kernel<OFF_WK ><<<blocks((size_t)2048*256),  256>>>(wk,  2048*256);
    round_copy_kernel<OFF_WV ><<<blocks((size_t)2048*256),  256>>>(wv,  2048*256);
    round_copy_kernel<OFF_WO ><<<blocks((size_t)2048*2048), 256>>>(wo,  2048*2048);
    round_copy_kernel<OFF_WG ><<<blocks((size_t)Ec*2048*IM),256>>>(wg,  Ec*2048*IM);
    round_copy_kernel<OFF_WU ><<<blocks((size_t)Ec*2048*IM),256>>>(wu,  Ec*2048*IM);
    round_copy_kernel<OFF_WD ><<<blocks((size_t)Ec*IM*2048),256>>>(wd,  Ec*IM*2048);
    round_copy_kernel<OFF_SWG><<<blocks((size_t)2048*ISH),  256>>>(swg, 2048*ISH);
    round_copy_kernel<OFF_SWU><<<blocks((size_t)2048*ISH),  256>>>(swu, 2048*ISH);
    round_copy_kernel<OFF_SWD><<<blocks((size_t)ISH*2048),  256>>>(swd, ISH*2048);

    clear_cnt_kernel<<<1, 32>>>();
    clear_moe_kernel<<<(Tc * Hc) / 256, 256>>>();

    // attention
    rmsnorm_kernel<0><<<Tc, 256>>>(x0, ln1);
    gemm_kernel<GM_Q><<<dim3(16, 32, 1), 128>>>(bq);
    gemm_kernel<GM_K><<<dim3(2, 32, 1), 128>>>(bk);
    gemm_kernel<GM_V><<<dim3(2, 32, 1), 128>>>(bv);
    rope_kernel<<<dim3(Tc, NQc + NKVc), 64>>>();
    kT_kernel<<<(Bc * NKVc * DHc * Sc) / 256, 256>>>();
    gemm_kernel<GM_SCORES><<<dim3(16, 16, 32), 128>>>(nullptr);
    softmax_kernel<<<Bc * NQc * Sc, 256>>>();
    gemm_kernel<GM_PV><<<dim3(1, 16, 32), 128>>>(nullptr);
    gemm_kernel<GM_O><<<dim3(16, 32, 1), 128>>>(x0);

    // MoE block
    rmsnorm_kernel<1><<<Tc, 256>>>(nullptr, ln2);
    router_kernel<<<Tc / 8, 256>>>(rw);
    gemm_kernel<GM_MG><<<dim3(11, 32, 8), 128>>>(nullptr);
    gemm_kernel<GM_MU><<<dim3(11, 32, 8), 128>>>(nullptr);
    moe_act_kernel<<<dim3(6, Tc, 8), 256>>>();
    gemm_kernel<GM_MD><<<dim3(16, 32, 8), 128>>>(nullptr);

    // shared expert
    gemm_kernel<GM_SG><<<dim3(44, 32, 1), 128>>>(nullptr);
    gemm_kernel<GM_SU><<<dim3(44, 32, 1), 128>>>(nullptr);
    shared_act_kernel<<<(size_t)(Tc) * ISH / 256, 256>>>();
    sgate_kernel<<<Tc / 8, 256>>>(sgw);
    gemm_kernel<GM_SD><<<dim3(16, 32, 1), 128>>>(nullptr);

    final_kernel<<<(Tc * Hc) / 256, 256>>>(out);
}